// round 7
// baseline (speedup 1.0000x reference)
#include <cuda_runtime.h>
#include <math.h>
#include <stdint.h>

// Problem constants
constexpr int Bc = 2, Sc = 2048, Dc = 256, Hc = 4, Lc = 4, Vc = 50257;
constexpr int HDc = 64, FFc = 1024;
constexpr int Mc = Bc * Sc;  // 4096 rows

// Scratch (device globals: allocation-guard-safe)
__device__ float g_h[Mc * Dc];
__device__ float g_n[Mc * Dc];
__device__ float g_q[Mc * Dc];
__device__ float g_k[Mc * Dc];
__device__ float g_v[Mc * Dc];
__device__ float g_att[Mc * Dc];
__device__ float g_f1[Mc * FFc];
__device__ float g_scores[(long)Bc * Hc * Sc * Sc];  // 134 MB

// ---------------------------------------------------------------------------
// Embedding: h[b,s,:] = tok_emb[id] + pos_emb[s]
// ---------------------------------------------------------------------------
__global__ void embed_k(const int* __restrict__ ids,
                        const float* __restrict__ tok,
                        const float* __restrict__ pos,
                        float* __restrict__ h) {
    int row = blockIdx.x;        // b*S + s
    int t = threadIdx.x;         // 0..255 == D
    int s = row % Sc;
    long id = ids[row];
    h[(long)row * Dc + t] = tok[id * Dc + t] + pos[(long)s * Dc + t];
}

// ---------------------------------------------------------------------------
// LayerNorm: block per row, 256 threads == D
// ---------------------------------------------------------------------------
__global__ void ln_k(const float* __restrict__ x, float* __restrict__ y,
                     const float* __restrict__ sc, const float* __restrict__ bi) {
    int row = blockIdx.x;
    int t = threadIdx.x;
    float v = x[(long)row * Dc + t];
    __shared__ float red[256];
    red[t] = v;
    __syncthreads();
    for (int s2 = 128; s2 > 0; s2 >>= 1) {
        if (t < s2) red[t] += red[t + s2];
        __syncthreads();
    }
    float mean = red[0] * (1.0f / Dc);
    __syncthreads();
    float d = v - mean;
    red[t] = d * d;
    __syncthreads();
    for (int s2 = 128; s2 > 0; s2 >>= 1) {
        if (t < s2) red[t] += red[t + s2];
        __syncthreads();
    }
    float var = red[0] * (1.0f / Dc);
    y[(long)row * Dc + t] = d * rsqrtf(var + 1e-5f) * sc[t] + bi[t];
}

// ---------------------------------------------------------------------------
// Generic NN GEMM: C = act(A@B + bias) (+R). 64x64x16 tiles, 4x4/thread.
// A tile k-major in smem; inner loop uses packed fma.rn.f32x2 (same exact
// numerics as scalar fmaf). Batched via blockIdx.z (used for AV).
// All NN uses have M,N mult of 64 and K mult of 16 -> no bounds checks.
// flags: 1=bias, 2=gelu(erf), 4=residual add (R), 8=causal K-truncation
//   (A rows are zero for k > global_row; K loop stops at m0+BM)
// ---------------------------------------------------------------------------
__global__ __launch_bounds__(256) void gemm_nn(
    const float* __restrict__ A, const float* __restrict__ Bm,
    const float* __restrict__ bias, const float* __restrict__ R,
    float* __restrict__ C, int K_, int lda, int ldb, int ldc,
    long sAz, long sBb, long sBh, long sCb, long sCh, int Hh, int flags) {
    __shared__ __align__(16) float As[16][68];  // k-major, 64 rows + 4 pad
    __shared__ __align__(16) float Bs[16][64];  // n-major; row = 256B aligned

    int z = blockIdx.z;
    int bb = z / Hh, hh = z % Hh;
    A += (long)z * sAz;
    Bm += (long)bb * sBb + (long)hh * sBh;
    C += (long)bb * sCb + (long)hh * sCh;
    if (R) R += (long)bb * sCb + (long)hh * sCh;

    int m0 = blockIdx.y * 64, n0 = blockIdx.x * 64;
    int tid = threadIdx.x, tx = tid & 15, ty = tid >> 4;

    int Keff = K_;
    if (flags & 8) Keff = min(K_, m0 + 64);  // probs rows zero beyond diagonal

    // A-load indices: 64x16 tile = 256 float4; one per thread
    int ar = tid >> 2, akq = (tid & 3) * 4;
    // B-load indices: 16x64 tile = 256 float4; one per thread
    int bkk = tid >> 4, bc4 = (tid & 15) * 4;

    // acc2[i][j] holds columns (2j, 2j+1) for row i as packed f32x2
    unsigned long long acc2[4][2];
#pragma unroll
    for (int i = 0; i < 4; i++)
#pragma unroll
        for (int j = 0; j < 2; j++) acc2[i][j] = 0ULL;

    for (int k0 = 0; k0 < Keff; k0 += 16) {
        float4 a4 = *(const float4*)&A[(long)(m0 + ar) * lda + k0 + akq];
        As[akq + 0][ar] = a4.x;
        As[akq + 1][ar] = a4.y;
        As[akq + 2][ar] = a4.z;
        As[akq + 3][ar] = a4.w;
        *(float4*)&Bs[bkk][bc4] =
            *(const float4*)&Bm[(long)(k0 + bkk) * ldb + n0 + bc4];
        __syncthreads();
#pragma unroll
        for (int kk = 0; kk < 16; kk++) {
            ulonglong2 bpv = *(const ulonglong2*)&Bs[kk][tx * 4];
            float4 a = *(const float4*)&As[kk][ty * 4];
            unsigned long long bp[2] = {bpv.x, bpv.y};
            float av[4] = {a.x, a.y, a.z, a.w};
#pragma unroll
            for (int i = 0; i < 4; i++) {
                unsigned long long ad;
                uint32_t au = __float_as_uint(av[i]);
                asm("mov.b64 %0, {%1, %1};" : "=l"(ad) : "r"(au));
#pragma unroll
                for (int j = 0; j < 2; j++) {
                    asm("fma.rn.f32x2 %0, %1, %2, %0;"
                        : "+l"(acc2[i][j]) : "l"(ad), "l"(bp[j]));
                }
            }
        }
        __syncthreads();
    }

#pragma unroll
    for (int i = 0; i < 4; i++) {
        int gm = m0 + ty * 4 + i;
#pragma unroll
        for (int j = 0; j < 2; j++) {
            uint32_t lo, hi;
            asm("mov.b64 {%0, %1}, %2;" : "=r"(lo), "=r"(hi) : "l"(acc2[i][j]));
            float rv[2] = {__uint_as_float(lo), __uint_as_float(hi)};
#pragma unroll
            for (int u = 0; u < 2; u++) {
                int gn = n0 + tx * 4 + 2 * j + u;
                float r_ = rv[u];
                if (flags & 1) r_ += bias[gn];
                if (flags & 2) r_ = 0.5f * r_ * (1.0f + erff(r_ * 0.70710678118654752f));
                if (flags & 4) r_ += R[(long)gm * ldc + gn];
                C[(long)gm * ldc + gn] = r_;
            }
        }
    }
}

// ---------------------------------------------------------------------------
// Generic NT GEMM: C = alpha * A @ B^T  (dot over last dim of both).
// 128x128x16 tiles, 8x8 per thread (256 threads). Both tiles k-major in smem.
// Inner loop uses packed fma.rn.f32x2 (FFMA2): 32 packed FMAs per kk instead
// of 64 scalar -> ~1.5x issue-slot reduction. Numerics identical to scalar.
// Used for attention scores (batched, causal block-skip) and logits (N edge).
// M must be a multiple of 128 (2048 and 4096 are). K multiple of 16.
// ---------------------------------------------------------------------------
__global__ __launch_bounds__(256) void gemm_nt(
    const float* __restrict__ A, const float* __restrict__ B2,
    float* __restrict__ C, int N_, int K_, int lda, int ldb, int ldc,
    long sAb, long sAh, long sBb, long sBh, long sCz, int Hh,
    float alpha, int causal) {
    int z = blockIdx.z;
    int bb = z / Hh, hh = z % Hh;
    A += (long)bb * sAb + (long)hh * sAh;
    B2 += (long)bb * sBb + (long)hh * sBh;
    C += (long)z * sCz;

    int m0 = blockIdx.y * 128, n0 = blockIdx.x * 128;
    if (causal && n0 > m0 + 127) return;  // wholly above diagonal: never read

    __shared__ __align__(16) float As[16][132];  // k-major, 128 rows + 4 pad
    __shared__ __align__(16) float Bs[16][132];  // k-major, 128 cols + 4 pad
    // row stride 132 floats = 528 B = 33*16 B -> float4/ulonglong2 stay aligned

    int tid = threadIdx.x, tx = tid & 15, ty = tid >> 4;  // tx: n, ty: m

    // Tile loads: 128x16 = 512 float4 each; two per thread.
    int lr0 = tid >> 2, lkq = (tid & 3) * 4;  // row 0..63 (+64 for i=1), k-quad

    // acc2[i][j] holds columns (2j, 2j+1) for row i as a packed f32x2.
    unsigned long long acc2[8][4];
#pragma unroll
    for (int i = 0; i < 8; i++)
#pragma unroll
        for (int j = 0; j < 4; j++) acc2[i][j] = 0ULL;  // both lanes = 0.0f

    for (int k0 = 0; k0 < K_; k0 += 16) {
#pragma unroll
        for (int i = 0; i < 2; i++) {
            int r = lr0 + i * 64;
            float4 a4 = *(const float4*)&A[(long)(m0 + r) * lda + k0 + lkq];
            As[lkq + 0][r] = a4.x;
            As[lkq + 1][r] = a4.y;
            As[lkq + 2][r] = a4.z;
            As[lkq + 3][r] = a4.w;
        }
#pragma unroll
        for (int i = 0; i < 2; i++) {
            int c = lr0 + i * 64;
            float4 b4 = make_float4(0.f, 0.f, 0.f, 0.f);
            if (n0 + c < N_)
                b4 = *(const float4*)&B2[(long)(n0 + c) * ldb + k0 + lkq];
            Bs[lkq + 0][c] = b4.x;
            Bs[lkq + 1][c] = b4.y;
            Bs[lkq + 2][c] = b4.z;
            Bs[lkq + 3][c] = b4.w;
        }
        __syncthreads();
#pragma unroll
        for (int kk = 0; kk < 16; kk++) {
            float4 a0 = *(const float4*)&As[kk][ty * 8];
            float4 a1 = *(const float4*)&As[kk][ty * 8 + 4];
            ulonglong2 bp01 = *(const ulonglong2*)&Bs[kk][tx * 8];
            ulonglong2 bp23 = *(const ulonglong2*)&Bs[kk][tx * 8 + 4];
            float av[8] = {a0.x, a0.y, a0.z, a0.w, a1.x, a1.y, a1.z, a1.w};
            unsigned long long bp[4] = {bp01.x, bp01.y, bp23.x, bp23.y};
#pragma unroll
            for (int i = 0; i < 8; i++) {
                unsigned long long ad;
                uint32_t au = __float_as_uint(av[i]);
                asm("mov.b64 %0, {%1, %1};" : "=l"(ad) : "r"(au));
#pragma unroll
                for (int j = 0; j < 4; j++) {
                    asm("fma.rn.f32x2 %0, %1, %2, %0;"
                        : "+l"(acc2[i][j]) : "l"(ad), "l"(bp[j]));
                }
            }
        }
        __syncthreads();
    }

#pragma unroll
    for (int i = 0; i < 8; i++) {
        int gm = m0 + ty * 8 + i;
#pragma unroll
        for (int j = 0; j < 4; j++) {
            uint32_t lo, hi;
            asm("mov.b64 {%0, %1}, %2;" : "=r"(lo), "=r"(hi) : "l"(acc2[i][j]));
            int gn = n0 + tx * 8 + 2 * j;
            if (gn < N_) C[(long)gm * ldc + gn] = __uint_as_float(lo) * alpha;
            if (gn + 1 < N_) C[(long)gm * ldc + gn + 1] = __uint_as_float(hi) * alpha;
        }
    }
}

// ---------------------------------------------------------------------------
// Causal softmax over row i: valid j in [0, i]; zeros written for j > i so the
// dense AV GEMM is correct. exp computed once per element (pass 2 stores it).
// ---------------------------------------------------------------------------
__global__ void softmax_k(float* __restrict__ scores) {
    long row = blockIdx.x;  // z*S + i  (offset row*S == z*S*S + i*S)
    float* p = scores + row * (long)Sc;
    int i = (int)(row & (Sc - 1));
    int nv = i + 1;
    int t = threadIdx.x;
    __shared__ float red[256];

    float m = -1e30f;
    for (int j = t; j < nv; j += 256) m = fmaxf(m, p[j]);
    red[t] = m;
    __syncthreads();
    for (int s2 = 128; s2 > 0; s2 >>= 1) {
        if (t < s2) red[t] = fmaxf(red[t], red[t + s2]);
        __syncthreads();
    }
    m = red[0];
    __syncthreads();

    float sum = 0.0f;
    for (int j = t; j < nv; j += 256) {
        float e = expf(p[j] - m);
        p[j] = e;          // store exp once; rescaled below
        sum += e;
    }
    red[t] = sum;
    __syncthreads();
    for (int s2 = 128; s2 > 0; s2 >>= 1) {
        if (t < s2) red[t] += red[t + s2];
        __syncthreads();
    }
    float inv = 1.0f / red[0];
    __syncthreads();

    for (int j = t; j < Sc; j += 256) {
        p[j] = (j < nv) ? p[j] * inv : 0.0f;
    }
}

// ---------------------------------------------------------------------------
extern "C" void kernel_launch(void* const* d_in, const int* in_sizes, int n_in,
                              void* d_out, int out_size) {
    const int* ids = (const int*)d_in[0];
    const float* tok = (const float*)d_in[1];
    const float* pos = (const float*)d_in[2];
    const float* Wq = (const float*)d_in[3];
    const float* bq = (const float*)d_in[4];
    const float* Wk = (const float*)d_in[5];
    const float* bk = (const float*)d_in[6];
    const float* Wv = (const float*)d_in[7];
    const float* bv = (const float*)d_in[8];
    const float* Wo = (const float*)d_in[9];
    const float* bo = (const float*)d_in[10];
    const float* ln1s = (const float*)d_in[11];
    const float* ln1b = (const float*)d_in[12];
    const float* ln2s = (const float*)d_in[13];
    const float* ln2b = (const float*)d_in[14];
    const float* W1 = (const float*)d_in[15];
    const float* b1 = (const float*)d_in[16];
    const float* W2 = (const float*)d_in[17];
    const float* b2 = (const float*)d_in[18];
    const float* lnfs = (const float*)d_in[19];
    const float* lnfb = (const float*)d_in[20];
    float* out = (float*)d_out;

    float *h, *n, *q, *k, *v, *att, *f1, *sc;
    cudaGetSymbolAddress((void**)&h, g_h);
    cudaGetSymbolAddress((void**)&n, g_n);
    cudaGetSymbolAddress((void**)&q, g_q);
    cudaGetSymbolAddress((void**)&k, g_k);
    cudaGetSymbolAddress((void**)&v, g_v);
    cudaGetSymbolAddress((void**)&att, g_att);
    cudaGetSymbolAddress((void**)&f1, g_f1);
    cudaGetSymbolAddress((void**)&sc, g_scores);

    embed_k<<<Mc, 256>>>(ids, tok, pos, h);

    dim3 gD(Dc / 64, Mc / 64, 1);            // 4 x 64
    dim3 gS(Sc / 128, Sc / 128, Bc * Hc);    // 16 x 16 x 8   (NT 128x128 tiles)
    dim3 gAV(1, Sc / 64, Bc * Hc);           // 1 x 32 x 8
    dim3 gF1(FFc / 64, Mc / 64, 1);          // 16 x 64
    dim3 gLG((Vc + 127) / 128, Mc / 128, 1); // 393 x 32

    for (int l = 0; l < Lc; l++) {
        ln_k<<<Mc, 256>>>(h, n, ln1s + l * Dc, ln1b + l * Dc);

        gemm_nn<<<gD, 256>>>(n, Wq + (long)l * Dc * Dc, bq + l * Dc, nullptr, q,
                             Dc, Dc, Dc, Dc, 0, 0, 0, 0, 0, 1, 1);
        gemm_nn<<<gD, 256>>>(n, Wk + (long)l * Dc * Dc, bk + l * Dc, nullptr, k,
                             Dc, Dc, Dc, Dc, 0, 0, 0, 0, 0, 1, 1);
        gemm_nn<<<gD, 256>>>(n, Wv + (long)l * Dc * Dc, bv + l * Dc, nullptr, v,
                             Dc, Dc, Dc, Dc, 0, 0, 0, 0, 0, 1, 1);

        // scores[z,i,j] = 0.125 * q[b,i,h*64:] . k[b,j,h*64:]
        gemm_nt<<<gS, 256>>>(q, k, sc, Sc, HDc, Dc, Dc, Sc,
                             (long)Sc * Dc, 64, (long)Sc * Dc, 64,
                             (long)Sc * Sc, Hc, 0.125f, 1);

        softmax_k<<<Bc * Hc * Sc, 256>>>(sc);

        // att[b,i,h*64:] = probs @ v   (K truncated at the diagonal)
        gemm_nn<<<gAV, 256>>>(sc, v, nullptr, nullptr, att, Sc, Sc, Dc, Dc,
                              (long)Sc * Sc, (long)Sc * Dc, 64,
                              (long)Sc * Dc, 64, Hc, 8);

        // h = h + att @ Wo + bo
        gemm_nn<<<gD, 256>>>(att, Wo + (long)l * Dc * Dc, bo + l * Dc, h, h,
                             Dc, Dc, Dc, Dc, 0, 0, 0, 0, 0, 1, 1 | 4);

        ln_k<<<Mc, 256>>>(h, n, ln2s + l * Dc, ln2b + l * Dc);

        // f1 = gelu(n @ W1 + b1)
        gemm_nn<<<gF1, 256>>>(n, W1 + (long)l * Dc * FFc, b1 + (long)l * FFc,
                              nullptr, f1, Dc, Dc, FFc, FFc, 0, 0, 0, 0, 0, 1,
                              1 | 2);

        // h = h + f1 @ W2 + b2
        gemm_nn<<<gD, 256>>>(f1, W2 + (long)l * FFc * Dc, b2 + l * Dc, h, h,
                             FFc, FFc, Dc, Dc, 0, 0, 0, 0, 0, 1, 1 | 4);
    }

    ln_k<<<Mc, 256>>>(h, n, lnfs, lnfb);

    // logits = n @ tok_emb^T
    gemm_nt<<<gLG, 256>>>(n, tok, out, Vc, Dc, Dc, Dc, Vc,
                          0, 0, 0, 0, 0, 1, 1.0f, 0);
}

// round 14
// speedup vs baseline: 1.3198x; 1.3198x over previous
#include <cuda_runtime.h>
#include <cuda_bf16.h>
#include <math.h>
#include <stdint.h>

// Problem constants
constexpr int Bc = 2, Sc = 2048, Dc = 256, Hc = 4, Lc = 4, Vc = 50257;
constexpr int HDc = 64, FFc = 1024;
constexpr int Mc = Bc * Sc;  // 4096 rows
constexpr int KBIG = 768;    // 3-term bf16-split K: [ah,ah,al]·[th,tl,th]
constexpr int VPAD = 50304;  // 393 * 128

// Scratch (device globals: allocation-guard-safe)
__device__ float g_h[Mc * Dc];
__device__ float g_n[Mc * Dc];
__device__ float g_q[Mc * Dc];
__device__ float g_k[Mc * Dc];
__device__ float g_v[Mc * Dc];
__device__ float g_att[Mc * Dc];
__device__ float g_f1[Mc * FFc];
__device__ float g_scores[(long)Bc * Hc * Sc * Sc];  // 134 MB
__device__ __nv_bfloat16 g_Abig[(long)Mc * KBIG];    // 6.3 MB
__device__ __nv_bfloat16 g_Bbig[(long)VPAD * KBIG];  // 77 MB

__device__ __forceinline__ uint32_t smem_u32(const void* p) {
    uint32_t a;
    asm("{ .reg .u64 t; cvta.to.shared.u64 t, %1; cvt.u32.u64 %0, t; }"
        : "=r"(a) : "l"(p));
    return a;
}

// ---------------------------------------------------------------------------
// Embedding
// ---------------------------------------------------------------------------
__global__ void embed_k(const int* __restrict__ ids,
                        const float* __restrict__ tok,
                        const float* __restrict__ pos,
                        float* __restrict__ h) {
    int row = blockIdx.x;
    int t = threadIdx.x;
    int s = row % Sc;
    long id = ids[row];
    h[(long)row * Dc + t] = tok[id * Dc + t] + pos[(long)s * Dc + t];
}

// ---------------------------------------------------------------------------
// LayerNorm
// ---------------------------------------------------------------------------
__global__ void ln_k(const float* __restrict__ x, float* __restrict__ y,
                     const float* __restrict__ sc, const float* __restrict__ bi) {
    int row = blockIdx.x;
    int t = threadIdx.x;
    float v = x[(long)row * Dc + t];
    __shared__ float red[256];
    red[t] = v;
    __syncthreads();
    for (int s2 = 128; s2 > 0; s2 >>= 1) {
        if (t < s2) red[t] += red[t + s2];
        __syncthreads();
    }
    float mean = red[0] * (1.0f / Dc);
    __syncthreads();
    float d = v - mean;
    red[t] = d * d;
    __syncthreads();
    for (int s2 = 128; s2 > 0; s2 >>= 1) {
        if (t < s2) red[t] += red[t + s2];
        __syncthreads();
    }
    float var = red[0] * (1.0f / Dc);
    y[(long)row * Dc + t] = d * rsqrtf(var + 1e-5f) * sc[t] + bi[t];
}

// ---------------------------------------------------------------------------
// bf16-split conversions: A'' = [ah, ah, al], B'' = [th, tl, th];
// sum over K=768 -> ah*th + ah*tl + al*th ~= a*t (rel err ~1e-4).
// ---------------------------------------------------------------------------
__global__ void convA_k(const float* __restrict__ n,
                        __nv_bfloat16* __restrict__ Abig) {
    int m = blockIdx.x, t = threadIdx.x;
    float v = n[(long)m * Dc + t];
    __nv_bfloat16 hi = __float2bfloat16(v);
    __nv_bfloat16 lo = __float2bfloat16(v - __bfloat162float(hi));
    Abig[(long)m * KBIG + t] = hi;
    Abig[(long)m * KBIG + 256 + t] = hi;
    Abig[(long)m * KBIG + 512 + t] = lo;
}
__global__ void convB_k(const float* __restrict__ tok,
                        __nv_bfloat16* __restrict__ Bbig) {
    int vr = blockIdx.x, t = threadIdx.x;
    float v = (vr < Vc) ? tok[(long)vr * Dc + t] : 0.0f;
    __nv_bfloat16 hi = __float2bfloat16(v);
    __nv_bfloat16 lo = __float2bfloat16(v - __bfloat162float(hi));
    Bbig[(long)vr * KBIG + t] = hi;
    Bbig[(long)vr * KBIG + 256 + t] = lo;
    Bbig[(long)vr * KBIG + 512 + t] = hi;
}

// ---------------------------------------------------------------------------
// Logits GEMM via mma.sync (bf16 HMMA, family-generic PTX — no 'a' features).
// C[128m x 128n] = Abig[128 x 768] @ Bbig[128 x 768]^T, fp32 accum.
// 8 warps as 2(m) x 4(n); warp tile 64x32 = 4x4 m16n8k16 tiles.
// smem rows padded to 80B (5x16B): ldmatrix-aligned, conflict-free.
// Epilogue uses SCALAR stores: Vc is odd, so float2 would misalign on odd rows.
// ---------------------------------------------------------------------------
#define LDSM4(r0, r1, r2, r3, addr) \
    asm volatile("ldmatrix.sync.aligned.m8n8.x4.shared.b16 {%0,%1,%2,%3}, [%4];" \
                 : "=r"(r0), "=r"(r1), "=r"(r2), "=r"(r3) : "r"(addr))
#define MMA16816(c0, c1, c2, c3, a0, a1, a2, a3, b0, b1) \
    asm volatile("mma.sync.aligned.m16n8k16.row.col.f32.bf16.bf16.f32 " \
                 "{%0,%1,%2,%3}, {%4,%5,%6,%7}, {%8,%9}, {%0,%1,%2,%3};" \
                 : "+f"(c0), "+f"(c1), "+f"(c2), "+f"(c3) \
                 : "r"(a0), "r"(a1), "r"(a2), "r"(a3), "r"(b0), "r"(b1))

constexpr int KT = 32;         // bf16 K per tile (64B)
constexpr int NKT = KBIG / KT; // 24
constexpr int SROW = 80;       // smem row stride bytes (64B data + 16B pad)

__global__ __launch_bounds__(256) void logits_mma_k(
    const __nv_bfloat16* __restrict__ Abig,
    const __nv_bfloat16* __restrict__ Bbig,
    float* __restrict__ out) {
    __shared__ __align__(16) uint8_t sA[2][128 * SROW];
    __shared__ __align__(16) uint8_t sB[2][128 * SROW];

    int tid = threadIdx.x, w = tid >> 5, lane = tid & 31;
    int n0 = blockIdx.x * 128, m0 = blockIdx.y * 128;
    int wm0 = (w & 1) * 64, wn0 = (w >> 1) * 32;

    float acc[4][4][4];
#pragma unroll
    for (int i = 0; i < 4; i++)
#pragma unroll
        for (int j = 0; j < 4; j++)
#pragma unroll
            for (int u = 0; u < 4; u++) acc[i][j][u] = 0.0f;

    uint4 pa[2], pb[2];
    auto loadg = [&](int c, uint4* da, uint4* db) {
#pragma unroll
        for (int i = 0; i < 2; i++) {
            int idx = tid + i * 256;      // 0..511
            int row = idx >> 2, quad = idx & 3;
            da[i] = *(const uint4*)(Abig + (long)(m0 + row) * KBIG + c * KT + quad * 8);
            db[i] = *(const uint4*)(Bbig + (long)(n0 + row) * KBIG + c * KT + quad * 8);
        }
    };
    loadg(0, pa, pb);

    for (int c = 0; c < NKT; c++) {
        int buf = c & 1;
#pragma unroll
        for (int i = 0; i < 2; i++) {
            int idx = tid + i * 256;
            int row = idx >> 2, quad = idx & 3;
            *(uint4*)(sA[buf] + row * SROW + quad * 16) = pa[i];
            *(uint4*)(sB[buf] + row * SROW + quad * 16) = pb[i];
        }
        __syncthreads();
        if (c + 1 < NKT) loadg(c + 1, pa, pb);

        uint32_t sa = smem_u32(sA[buf]);
        uint32_t sb = smem_u32(sB[buf]);

        // B fragments: 4 n-tiles, each x4 ldmatrix covers all k=32
        uint32_t b[4][4];
#pragma unroll
        for (int tn = 0; tn < 4; tn++) {
            uint32_t addr = sb + (wn0 + tn * 8 + (lane & 7)) * SROW + (lane >> 3) * 16;
            LDSM4(b[tn][0], b[tn][1], b[tn][2], b[tn][3], addr);
        }
#pragma unroll
        for (int ks = 0; ks < 2; ks++) {
            uint32_t a[4][4];
#pragma unroll
            for (int tm = 0; tm < 4; tm++) {
                uint32_t addr = sa + (wm0 + tm * 16 + (lane & 15)) * SROW +
                                (lane >> 4) * 16 + ks * 32;
                LDSM4(a[tm][0], a[tm][1], a[tm][2], a[tm][3], addr);
            }
#pragma unroll
            for (int tm = 0; tm < 4; tm++)
#pragma unroll
                for (int tn = 0; tn < 4; tn++)
                    MMA16816(acc[tm][tn][0], acc[tm][tn][1], acc[tm][tn][2],
                             acc[tm][tn][3], a[tm][0], a[tm][1], a[tm][2],
                             a[tm][3], b[tn][2 * ks], b[tn][2 * ks + 1]);
        }
        __syncthreads();
    }

    // Epilogue: d0,d1 -> row lane/4, cols 2*(lane%4)+{0,1}; d2,d3 -> row+8.
    // Scalar stores only (Vc odd -> odd-row float2 would be misaligned).
#pragma unroll
    for (int tm = 0; tm < 4; tm++) {
        long gr0 = m0 + wm0 + tm * 16 + (lane >> 2);
#pragma unroll
        for (int tn = 0; tn < 4; tn++) {
            int col = n0 + wn0 + tn * 8 + (lane & 3) * 2;
            if (col < Vc) {
                out[gr0 * Vc + col] = acc[tm][tn][0];
                out[(gr0 + 8) * Vc + col] = acc[tm][tn][2];
            }
            if (col + 1 < Vc) {
                out[gr0 * Vc + col + 1] = acc[tm][tn][1];
                out[(gr0 + 8) * Vc + col + 1] = acc[tm][tn][3];
            }
        }
    }
}

// ---------------------------------------------------------------------------
// NN GEMM (f32x2 FFMA2), 64x64x16, 4x4/thread — unchanged from passing R7.
// flags: 1=bias, 2=gelu, 4=residual, 8=causal K-truncation
// ---------------------------------------------------------------------------
__global__ __launch_bounds__(256) void gemm_nn(
    const float* __restrict__ A, const float* __restrict__ Bm,
    const float* __restrict__ bias, const float* __restrict__ R,
    float* __restrict__ C, int K_, int lda, int ldb, int ldc,
    long sAz, long sBb, long sBh, long sCb, long sCh, int Hh, int flags) {
    __shared__ __align__(16) float As[16][68];
    __shared__ __align__(16) float Bs[16][64];

    int z = blockIdx.z;
    int bb = z / Hh, hh = z % Hh;
    A += (long)z * sAz;
    Bm += (long)bb * sBb + (long)hh * sBh;
    C += (long)bb * sCb + (long)hh * sCh;
    if (R) R += (long)bb * sCb + (long)hh * sCh;

    int m0 = blockIdx.y * 64, n0 = blockIdx.x * 64;
    int tid = threadIdx.x, tx = tid & 15, ty = tid >> 4;

    int Keff = K_;
    if (flags & 8) Keff = min(K_, m0 + 64);

    int ar = tid >> 2, akq = (tid & 3) * 4;
    int bkk = tid >> 4, bc4 = (tid & 15) * 4;

    unsigned long long acc2[4][2];
#pragma unroll
    for (int i = 0; i < 4; i++)
#pragma unroll
        for (int j = 0; j < 2; j++) acc2[i][j] = 0ULL;

    for (int k0 = 0; k0 < Keff; k0 += 16) {
        float4 a4 = *(const float4*)&A[(long)(m0 + ar) * lda + k0 + akq];
        As[akq + 0][ar] = a4.x;
        As[akq + 1][ar] = a4.y;
        As[akq + 2][ar] = a4.z;
        As[akq + 3][ar] = a4.w;
        *(float4*)&Bs[bkk][bc4] =
            *(const float4*)&Bm[(long)(k0 + bkk) * ldb + n0 + bc4];
        __syncthreads();
#pragma unroll
        for (int kk = 0; kk < 16; kk++) {
            ulonglong2 bpv = *(const ulonglong2*)&Bs[kk][tx * 4];
            float4 a = *(const float4*)&As[kk][ty * 4];
            unsigned long long bp[2] = {bpv.x, bpv.y};
            float av[4] = {a.x, a.y, a.z, a.w};
#pragma unroll
            for (int i = 0; i < 4; i++) {
                unsigned long long ad;
                uint32_t au = __float_as_uint(av[i]);
                asm("mov.b64 %0, {%1, %1};" : "=l"(ad) : "r"(au));
#pragma unroll
                for (int j = 0; j < 2; j++) {
                    asm("fma.rn.f32x2 %0, %1, %2, %0;"
                        : "+l"(acc2[i][j]) : "l"(ad), "l"(bp[j]));
                }
            }
        }
        __syncthreads();
    }

#pragma unroll
    for (int i = 0; i < 4; i++) {
        int gm = m0 + ty * 4 + i;
#pragma unroll
        for (int j = 0; j < 2; j++) {
            uint32_t lo, hi;
            asm("mov.b64 {%0, %1}, %2;" : "=r"(lo), "=r"(hi) : "l"(acc2[i][j]));
            float rv[2] = {__uint_as_float(lo), __uint_as_float(hi)};
#pragma unroll
            for (int u = 0; u < 2; u++) {
                int gn = n0 + tx * 4 + 2 * j + u;
                float r_ = rv[u];
                if (flags & 1) r_ += bias[gn];
                if (flags & 2) r_ = 0.5f * r_ * (1.0f + erff(r_ * 0.70710678118654752f));
                if (flags & 4) r_ += R[(long)gm * ldc + gn];
                C[(long)gm * ldc + gn] = r_;
            }
        }
    }
}

// ---------------------------------------------------------------------------
// NT GEMM (f32x2 FFMA2), 128x128x16, 8x8/thread — attention scores only.
// ---------------------------------------------------------------------------
__global__ __launch_bounds__(256) void gemm_nt(
    const float* __restrict__ A, const float* __restrict__ B2,
    float* __restrict__ C, int N_, int K_, int lda, int ldb, int ldc,
    long sAb, long sAh, long sBb, long sBh, long sCz, int Hh,
    float alpha, int causal) {
    int z = blockIdx.z;
    int bb = z / Hh, hh = z % Hh;
    A += (long)bb * sAb + (long)hh * sAh;
    B2 += (long)bb * sBb + (long)hh * sBh;
    C += (long)z * sCz;

    int m0 = blockIdx.y * 128, n0 = blockIdx.x * 128;
    if (causal && n0 > m0 + 127) return;

    __shared__ __align__(16) float As[16][132];
    __shared__ __align__(16) float Bs[16][132];

    int tid = threadIdx.x, tx = tid & 15, ty = tid >> 4;
    int lr0 = tid >> 2, lkq = (tid & 3) * 4;

    unsigned long long acc2[8][4];
#pragma unroll
    for (int i = 0; i < 8; i++)
#pragma unroll
        for (int j = 0; j < 4; j++) acc2[i][j] = 0ULL;

    for (int k0 = 0; k0 < K_; k0 += 16) {
#pragma unroll
        for (int i = 0; i < 2; i++) {
            int r = lr0 + i * 64;
            float4 a4 = *(const float4*)&A[(long)(m0 + r) * lda + k0 + lkq];
            As[lkq + 0][r] = a4.x;
            As[lkq + 1][r] = a4.y;
            As[lkq + 2][r] = a4.z;
            As[lkq + 3][r] = a4.w;
        }
#pragma unroll
        for (int i = 0; i < 2; i++) {
            int cidx = lr0 + i * 64;
            float4 b4 = make_float4(0.f, 0.f, 0.f, 0.f);
            if (n0 + cidx < N_)
                b4 = *(const float4*)&B2[(long)(n0 + cidx) * ldb + k0 + lkq];
            Bs[lkq + 0][cidx] = b4.x;
            Bs[lkq + 1][cidx] = b4.y;
            Bs[lkq + 2][cidx] = b4.z;
            Bs[lkq + 3][cidx] = b4.w;
        }
        __syncthreads();
#pragma unroll
        for (int kk = 0; kk < 16; kk++) {
            float4 a0 = *(const float4*)&As[kk][ty * 8];
            float4 a1 = *(const float4*)&As[kk][ty * 8 + 4];
            ulonglong2 bp01 = *(const ulonglong2*)&Bs[kk][tx * 8];
            ulonglong2 bp23 = *(const ulonglong2*)&Bs[kk][tx * 8 + 4];
            float av[8] = {a0.x, a0.y, a0.z, a0.w, a1.x, a1.y, a1.z, a1.w};
            unsigned long long bp[4] = {bp01.x, bp01.y, bp23.x, bp23.y};
#pragma unroll
            for (int i = 0; i < 8; i++) {
                unsigned long long ad;
                uint32_t au = __float_as_uint(av[i]);
                asm("mov.b64 %0, {%1, %1};" : "=l"(ad) : "r"(au));
#pragma unroll
                for (int j = 0; j < 4; j++) {
                    asm("fma.rn.f32x2 %0, %1, %2, %0;"
                        : "+l"(acc2[i][j]) : "l"(ad), "l"(bp[j]));
                }
            }
        }
        __syncthreads();
    }

#pragma unroll
    for (int i = 0; i < 8; i++) {
        int gm = m0 + ty * 8 + i;
#pragma unroll
        for (int j = 0; j < 4; j++) {
            uint32_t lo, hi;
            asm("mov.b64 {%0, %1}, %2;" : "=r"(lo), "=r"(hi) : "l"(acc2[i][j]));
            int gn = n0 + tx * 8 + 2 * j;
            if (gn < N_) C[(long)gm * ldc + gn] = __uint_as_float(lo) * alpha;
            if (gn + 1 < N_) C[(long)gm * ldc + gn + 1] = __uint_as_float(hi) * alpha;
        }
    }
}

// ---------------------------------------------------------------------------
// Causal softmax (exp computed once; zeros above diagonal)
// ---------------------------------------------------------------------------
__global__ void softmax_k(float* __restrict__ scores) {
    long row = blockIdx.x;
    float* p = scores + row * (long)Sc;
    int i = (int)(row & (Sc - 1));
    int nv = i + 1;
    int t = threadIdx.x;
    __shared__ float red[256];

    float m = -1e30f;
    for (int j = t; j < nv; j += 256) m = fmaxf(m, p[j]);
    red[t] = m;
    __syncthreads();
    for (int s2 = 128; s2 > 0; s2 >>= 1) {
        if (t < s2) red[t] = fmaxf(red[t], red[t + s2]);
        __syncthreads();
    }
    m = red[0];
    __syncthreads();

    float sum = 0.0f;
    for (int j = t; j < nv; j += 256) {
        float e = expf(p[j] - m);
        p[j] = e;
        sum += e;
    }
    red[t] = sum;
    __syncthreads();
    for (int s2 = 128; s2 > 0; s2 >>= 1) {
        if (t < s2) red[t] += red[t + s2];
        __syncthreads();
    }
    float inv = 1.0f / red[0];
    __syncthreads();

    for (int j = t; j < Sc; j += 256) {
        p[j] = (j < nv) ? p[j] * inv : 0.0f;
    }
}

// ---------------------------------------------------------------------------
extern "C" void kernel_launch(void* const* d_in, const int* in_sizes, int n_in,
                              void* d_out, int out_size) {
    const int* ids = (const int*)d_in[0];
    const float* tok = (const float*)d_in[1];
    const float* pos = (const float*)d_in[2];
    const float* Wq = (const float*)d_in[3];
    const float* bq = (const float*)d_in[4];
    const float* Wk = (const float*)d_in[5];
    const float* bk = (const float*)d_in[6];
    const float* Wv = (const float*)d_in[7];
    const float* bv = (const float*)d_in[8];
    const float* Wo = (const float*)d_in[9];
    const float* bo = (const float*)d_in[10];
    const float* ln1s = (const float*)d_in[11];
    const float* ln1b = (const float*)d_in[12];
    const float* ln2s = (const float*)d_in[13];
    const float* ln2b = (const float*)d_in[14];
    const float* W1 = (const float*)d_in[15];
    const float* b1 = (const float*)d_in[16];
    const float* W2 = (const float*)d_in[17];
    const float* b2 = (const float*)d_in[18];
    const float* lnfs = (const float*)d_in[19];
    const float* lnfb = (const float*)d_in[20];
    float* out = (float*)d_out;

    float *h, *n, *q, *k, *v, *att, *f1, *sc;
    __nv_bfloat16 *Abig, *Bbig;
    cudaGetSymbolAddress((void**)&h, g_h);
    cudaGetSymbolAddress((void**)&n, g_n);
    cudaGetSymbolAddress((void**)&q, g_q);
    cudaGetSymbolAddress((void**)&k, g_k);
    cudaGetSymbolAddress((void**)&v, g_v);
    cudaGetSymbolAddress((void**)&att, g_att);
    cudaGetSymbolAddress((void**)&f1, g_f1);
    cudaGetSymbolAddress((void**)&sc, g_scores);
    cudaGetSymbolAddress((void**)&Abig, g_Abig);
    cudaGetSymbolAddress((void**)&Bbig, g_Bbig);

    embed_k<<<Mc, 256>>>(ids, tok, pos, h);
    convB_k<<<VPAD, 256>>>(tok, Bbig);  // independent of layers

    dim3 gD(Dc / 64, Mc / 64, 1);
    dim3 gS(Sc / 128, Sc / 128, Bc * Hc);
    dim3 gAV(1, Sc / 64, Bc * Hc);
    dim3 gF1(FFc / 64, Mc / 64, 1);

    for (int l = 0; l < Lc; l++) {
        ln_k<<<Mc, 256>>>(h, n, ln1s + l * Dc, ln1b + l * Dc);

        gemm_nn<<<gD, 256>>>(n, Wq + (long)l * Dc * Dc, bq + l * Dc, nullptr, q,
                             Dc, Dc, Dc, Dc, 0, 0, 0, 0, 0, 1, 1);
        gemm_nn<<<gD, 256>>>(n, Wk + (long)l * Dc * Dc, bk + l * Dc, nullptr, k,
                             Dc, Dc, Dc, Dc, 0, 0, 0, 0, 0, 1, 1);
        gemm_nn<<<gD, 256>>>(n, Wv + (long)l * Dc * Dc, bv + l * Dc, nullptr, v,
                             Dc, Dc, Dc, Dc, 0, 0, 0, 0, 0, 1, 1);

        gemm_nt<<<gS, 256>>>(q, k, sc, Sc, HDc, Dc, Dc, Sc,
                             (long)Sc * Dc, 64, (long)Sc * Dc, 64,
                             (long)Sc * Sc, Hc, 0.125f, 1);

        softmax_k<<<Bc * Hc * Sc, 256>>>(sc);

        gemm_nn<<<gAV, 256>>>(sc, v, nullptr, nullptr, att, Sc, Sc, Dc, Dc,
                              (long)Sc * Sc, (long)Sc * Dc, 64,
                              (long)Sc * Dc, 64, Hc, 8);

        gemm_nn<<<gD, 256>>>(att, Wo + (long)l * Dc * Dc, bo + l * Dc, h, h,
                             Dc, Dc, Dc, Dc, 0, 0, 0, 0, 0, 1, 1 | 4);

        ln_k<<<Mc, 256>>>(h, n, ln2s + l * Dc, ln2b + l * Dc);

        gemm_nn<<<gF1, 256>>>(n, W1 + (long)l * Dc * FFc, b1 + (long)l * FFc,
                              nullptr, f1, Dc, Dc, FFc, FFc, 0, 0, 0, 0, 0, 1,
                              1 | 2);

        gemm_nn<<<gD, 256>>>(f1, W2 + (long)l * FFc * Dc, b2 + l * Dc, h, h,
                             FFc, FFc, Dc, Dc, 0, 0, 0, 0, 0, 1, 1 | 4);
    }

    ln_k<<<Mc, 256>>>(h, n, lnfs, lnfb);
    convA_k<<<Mc, 256>>>(n, Abig);

    // logits = n @ tok_emb^T via bf16-split mma.sync
    logits_mma_k<<<dim3(VPAD / 128, Mc / 128), 256>>>(Abig, Bbig, out);
}